// round 13
// baseline (speedup 1.0000x reference)
#include <cuda_runtime.h>
#include <math.h>

// Problem constants (fixed shapes for this problem instance)
#define Zc 512
#define Hc 256
#define NMAX 20000
#define BMAX 32
#define DPB 16     // docs per block in doc kernel (4 per thread) — R7 optimum
#define SDOCS 8    // docs per block in score kernel
#define KMAX 8     // final output k bound
#define K1 8       // per-warp candidate depth in stage1
#define SEG 16     // stage-1 segments per query (x4 warps = 64 slices)
#define NCAND (SEG * 4 * K1)   // 512 candidates per query

// Scratch (no allocations allowed anywhere)
__device__ float g_qb[BMAX * Hc];                 // qa + b1, [B,H]
__device__ float g_da[(size_t)NMAX * Hc];         // d_t @ W1[H:], [N,H]
__device__ float g_scores[(size_t)BMAX * NMAX];   // APPROX scaled scores [B,N]
__device__ unsigned long long g_part[BMAX * NCAND]; // stage-1 candidate keys

typedef unsigned long long u64;

__device__ __forceinline__ u64 pk2(float a, float b) {
    u64 r; asm("mov.b64 %0, {%1,%2};" : "=l"(r) : "f"(a), "f"(b)); return r;
}
__device__ __forceinline__ void fma2(u64 &d, u64 a, u64 b) {
    asm("fma.rn.f32x2 %0, %1, %2, %0;" : "+l"(d) : "l"(a), "l"(b));
}
__device__ __forceinline__ float2 up2(u64 v) {
    float lo, hi; asm("mov.b64 {%0,%1}, %2;" : "=f"(lo), "=f"(hi) : "l"(v));
    return make_float2(lo, hi);
}

__device__ __forceinline__ float gelu_f(float x) {
    // exact gelu: 0.5*x*(1+erf(x/sqrt(2)))
    return 0.5f * x * (1.0f + erff(x * 0.70710678118654752440f));
}

// fast approximate gelu core WITHOUT the 0.5 factor (folded into weights):
// returns x*(1+tanh(0.79788456*x + 0.03567741*x^3)) — approx pass only.
__device__ __forceinline__ float gelu_a2(float x) {
    float x2 = x * x;
    float inner = x * fmaf(0.035677408136f, x2, 0.7978845608028654f);
    float th;
    asm("tanh.approx.f32 %0, %1;" : "=f"(th) : "f"(inner));
    return x * (1.0f + th);
}

// ---------------------------------------------------------------------------
// Kernel 1: query path.  grid = B, block = 256 (one thread per h)
// ---------------------------------------------------------------------------
__global__ __launch_bounds__(256) void query_kernel(
    const float* __restrict__ q, const float* __restrict__ Wq,
    const float* __restrict__ bq, const float* __restrict__ lnw,
    const float* __restrict__ lnb, const float* __restrict__ W1,
    const float* __restrict__ b1)
{
    __shared__ float xq[Zc];
    __shared__ float qt[Hc];
    __shared__ float red[18];
    int b = blockIdx.x, t = threadIdx.x;
    const float* row = q + (size_t)b * Zc;
    for (int i = t; i < Zc; i += 256) xq[i] = row[i];
    __syncthreads();

    float acc = bq[t];
    #pragma unroll 8
    for (int z = 0; z < Zc; z++) acc = fmaf(xq[z], Wq[z * Hc + t], acc);
    float g = gelu_f(acc);

    float s = g, s2 = g * g;
    #pragma unroll
    for (int o = 16; o; o >>= 1) {
        s  += __shfl_down_sync(0xffffffffu, s, o);
        s2 += __shfl_down_sync(0xffffffffu, s2, o);
    }
    if ((t & 31) == 0) { red[t >> 5] = s; red[8 + (t >> 5)] = s2; }
    __syncthreads();
    if (t == 0) {
        float S = 0.f, S2 = 0.f;
        for (int w = 0; w < 8; w++) { S += red[w]; S2 += red[8 + w]; }
        float mu = S / (float)Hc;
        red[16] = mu;
        red[17] = S2 / (float)Hc - mu * mu;
    }
    __syncthreads();
    float mu = red[16], var = red[17];
    float v = (g - mu) * rsqrtf(var + 1e-5f) * lnw[t] + lnb[t];
    qt[t] = v;
    __syncthreads();

    float a2 = b1[t];  // fold b1 here
    #pragma unroll 8
    for (int j = 0; j < Hc; j++) a2 = fmaf(qt[j], W1[j * Hc + t], a2);
    g_qb[b * Hc + t] = a2;
}

// ---------------------------------------------------------------------------
// Kernel 2: doc path, fused — EXACT R7 configuration (proven 395.9us run).
// grid = N/DPB, block = 256, 48 KB static smem.
// hg = tid&63 owns h = 4*hg..4*hg+3; ds = tid>>6 owns docs {ds,ds+4,ds+8,ds+12}.
// ---------------------------------------------------------------------------
__global__ __launch_bounds__(256) void doc_kernel(
    const float* __restrict__ docs, const float* __restrict__ Wd,
    const float* __restrict__ bd, const float* __restrict__ lnw,
    const float* __restrict__ lnb, const float* __restrict__ W1, int N)
{
    __shared__ float xs[DPB][Zc];   // 32 KB: raw doc rows
    __shared__ float dt[DPB][Hc];   // 16 KB: activations
    int t = threadIdx.x;
    int hg = t & 63, ds = t >> 6;
    int h4 = hg * 4;
    int docBase = blockIdx.x * DPB;

    const float4* src = (const float4*)(docs + (size_t)docBase * Zc);
    float4* dstp = (float4*)&xs[0][0];
    #pragma unroll
    for (int i = t; i < DPB * Zc / 4; i += 256) dstp[i] = src[i];
    __syncthreads();

    // GEMM1: d = x @ Wd + bd  (each thread: 4h x 4docs, packed f32x2 over h)
    float4 bd4 = *(const float4*)&bd[h4];
    u64 aA[4], aB[4];
    {
        u64 bdA = pk2(bd4.x, bd4.y), bdB = pk2(bd4.z, bd4.w);
        #pragma unroll
        for (int i = 0; i < 4; i++) { aA[i] = bdA; aB[i] = bdB; }
    }
    for (int z4 = 0; z4 < Zc / 4; z4++) {
        float4 x0 = *(const float4*)&xs[ds][z4 * 4];
        float4 x1 = *(const float4*)&xs[ds + 4][z4 * 4];
        float4 x2 = *(const float4*)&xs[ds + 8][z4 * 4];
        float4 x3 = *(const float4*)&xs[ds + 12][z4 * 4];
        float xv[4][4] = {{x0.x, x0.y, x0.z, x0.w}, {x1.x, x1.y, x1.z, x1.w},
                          {x2.x, x2.y, x2.z, x2.w}, {x3.x, x3.y, x3.z, x3.w}};
        #pragma unroll
        for (int u = 0; u < 4; u++) {
            const u64* wp64 = (const u64*)&Wd[(size_t)(z4 * 4 + u) * Hc + h4];
            u64 wA = wp64[0], wB = wp64[1];
            #pragma unroll
            for (int i = 0; i < 4; i++) {
                u64 xx = pk2(xv[i][u], xv[i][u]);
                fma2(aA[i], wA, xx);
                fma2(aB[i], wB, xx);
            }
        }
    }
    #pragma unroll
    for (int i = 0; i < 4; i++) {
        float2 pA = up2(aA[i]), pB = up2(aB[i]);
        dt[ds + 4 * i][h4 + 0] = gelu_f(pA.x);
        dt[ds + 4 * i][h4 + 1] = gelu_f(pA.y);
        dt[ds + 4 * i][h4 + 2] = gelu_f(pB.x);
        dt[ds + 4 * i][h4 + 3] = gelu_f(pB.y);
    }
    __syncthreads();

    // LayerNorm per doc: warp w normalizes docs 2w, 2w+1
    {
        int wid = t >> 5, lane = t & 31;
        #pragma unroll
        for (int dd = 0; dd < 2; dd++) {
            float* r = dt[wid * 2 + dd];
            float s = 0.f, s2 = 0.f;
            #pragma unroll
            for (int j = lane; j < Hc; j += 32) { float v = r[j]; s += v; s2 += v * v; }
            #pragma unroll
            for (int o = 16; o; o >>= 1) {
                s  += __shfl_xor_sync(0xffffffffu, s, o);
                s2 += __shfl_xor_sync(0xffffffffu, s2, o);
            }
            float mu = s / (float)Hc;
            float rin = rsqrtf(s2 / (float)Hc - mu * mu + 1e-5f);
            #pragma unroll
            for (int j = lane; j < Hc; j += 32)
                r[j] = (r[j] - mu) * rin * lnw[j] + lnb[j];
        }
    }
    __syncthreads();

    // GEMM2: da = dt @ W1[H:2H]  (packed f32x2; weights via u64 reinterpret)
    u64 cA[4], cB[4];
    {
        u64 z = pk2(0.f, 0.f);
        #pragma unroll
        for (int i = 0; i < 4; i++) { cA[i] = z; cB[i] = z; }
    }
    for (int j4 = 0; j4 < Hc / 4; j4++) {
        float4 x0 = *(const float4*)&dt[ds][j4 * 4];
        float4 x1 = *(const float4*)&dt[ds + 4][j4 * 4];
        float4 x2 = *(const float4*)&dt[ds + 8][j4 * 4];
        float4 x3 = *(const float4*)&dt[ds + 12][j4 * 4];
        float xv[4][4] = {{x0.x, x0.y, x0.z, x0.w}, {x1.x, x1.y, x1.z, x1.w},
                          {x2.x, x2.y, x2.z, x2.w}, {x3.x, x3.y, x3.z, x3.w}};
        #pragma unroll
        for (int u = 0; u < 4; u++) {
            const u64* wp64 = (const u64*)&W1[(size_t)(Hc + j4 * 4 + u) * Hc + h4];
            u64 wA = wp64[0], wB = wp64[1];
            #pragma unroll
            for (int i = 0; i < 4; i++) {
                u64 xx = pk2(xv[i][u], xv[i][u]);
                fma2(cA[i], wA, xx);
                fma2(cB[i], wB, xx);
            }
        }
    }
    #pragma unroll
    for (int i = 0; i < 4; i++) {
        float2 pA = up2(cA[i]), pB = up2(cB[i]);
        ((float4*)&g_da[(size_t)(docBase + ds + 4 * i) * Hc])[hg] =
            make_float4(pA.x, pA.y, pB.x, pB.y);
    }
}

// ---------------------------------------------------------------------------
// Kernel 3: APPROXIMATE pairwise scoring — R7 scalar structure (proven).
// grid = N/SDOCS, block = 256.  d-outer / b-inner, dv hoisted per doc,
// 4 independent accumulator chains; 0.5 of gelu folded into the weights
// (approx path only — winners re-scored exactly in rerank).
// ---------------------------------------------------------------------------
__global__ __launch_bounds__(256) void score_kernel(
    const float* __restrict__ W2, const float* __restrict__ b2,
    const float* __restrict__ temp, int N)
{
    __shared__ float qbs[BMAX * Hc];   // 32 KB
    __shared__ float das[SDOCS][Hc];   // 8 KB
    __shared__ float w2s[Hc];
    int t = threadIdx.x;

    const float4* qsrc = (const float4*)g_qb;
    float4* qdst = (float4*)qbs;
    #pragma unroll
    for (int i = t; i < BMAX * Hc / 4; i += 256) qdst[i] = qsrc[i];
    w2s[t] = W2[t];
    int docBase = blockIdx.x * SDOCS;
    {
        const float4* dsrc = (const float4*)(g_da + (size_t)docBase * Hc);
        float4* ddst = (float4*)&das[0][0];
        ddst[t] = dsrc[t];
        ddst[t + 256] = dsrc[t + 256];
    }
    __syncthreads();

    float invt = 1.0f / (fabsf(temp[0]) + 1e-8f);
    float bb = b2[0];
    int w = t >> 5, lane = t & 31;

    float wv[8];
    #pragma unroll
    for (int j = 0; j < 8; j++) wv[j] = 0.5f * w2s[lane + 32 * j];

    float qv[4][8];
    #pragma unroll
    for (int bi = 0; bi < 4; bi++) {
        const float* qrow = &qbs[(w + 8 * bi) * Hc];
        #pragma unroll
        for (int j = 0; j < 8; j++) qv[bi][j] = qrow[lane + 32 * j];
    }

    #pragma unroll
    for (int d = 0; d < SDOCS; d++) {
        float dv[8];
        #pragma unroll
        for (int j = 0; j < 8; j++) dv[j] = das[d][lane + 32 * j];
        float acc0 = 0.f, acc1 = 0.f, acc2 = 0.f, acc3 = 0.f;
        #pragma unroll
        for (int j = 0; j < 8; j++) {
            float wj = wv[j], dj = dv[j];
            acc0 = fmaf(gelu_a2(qv[0][j] + dj), wj, acc0);
            acc1 = fmaf(gelu_a2(qv[1][j] + dj), wj, acc1);
            acc2 = fmaf(gelu_a2(qv[2][j] + dj), wj, acc2);
            acc3 = fmaf(gelu_a2(qv[3][j] + dj), wj, acc3);
        }
        #pragma unroll
        for (int o = 16; o; o >>= 1) {
            acc0 += __shfl_down_sync(0xffffffffu, acc0, o);
            acc1 += __shfl_down_sync(0xffffffffu, acc1, o);
            acc2 += __shfl_down_sync(0xffffffffu, acc2, o);
            acc3 += __shfl_down_sync(0xffffffffu, acc3, o);
        }
        if (lane == 0) {
            g_scores[(size_t)(w +  0) * N + docBase + d] = (acc0 + bb) * invt;
            g_scores[(size_t)(w +  8) * N + docBase + d] = (acc1 + bb) * invt;
            g_scores[(size_t)(w + 16) * N + docBase + d] = (acc2 + bb) * invt;
            g_scores[(size_t)(w + 24) * N + docBase + d] = (acc3 + bb) * invt;
        }
    }
}

// ---------------------------------------------------------------------------
// Top-k keys: (score, index) packed into one orderable uint64.
// Tie-break: equal score -> smaller index (low word = ~index).
// ---------------------------------------------------------------------------
__device__ __forceinline__ unsigned long long pack_key(float s, int i) {
    unsigned int u = __float_as_uint(s);
    u = (u & 0x80000000u) ? ~u : (u | 0x80000000u);
    return ((unsigned long long)u << 32) | (unsigned int)(~(unsigned int)i);
}

// ---------------------------------------------------------------------------
// Kernel 4a: per-warp top-8 candidates (approx scores). grid=(SEG,B), b=128.
// Pure shuffle argmax, no block barriers.  64 slices x 8 = 512 cands/query.
// ---------------------------------------------------------------------------
__global__ __launch_bounds__(128) void topk_stage1(int N)
{
    int seg = blockIdx.x, b = blockIdx.y, t = threadIdx.x;
    int nseg = gridDim.x;
    int seglen = (N + nseg - 1) / nseg;
    int start = seg * seglen;
    int end = start + seglen; if (end > N) end = N;

    unsigned long long loc[K1];
    #pragma unroll
    for (int j = 0; j < K1; j++) loc[j] = 0ull;

    const float* row = g_scores + (size_t)b * N;
    for (int i = start + t; i < end; i += 128) {
        unsigned long long key = pack_key(row[i], i);
        if (key > loc[K1 - 1]) {
            #pragma unroll
            for (int j = 0; j < K1; j++) {
                unsigned long long cur = loc[j];
                bool gt = key > cur;
                loc[j] = gt ? key : cur;
                key    = gt ? cur : key;
            }
        }
    }

    int wid = t >> 5, lane = t & 31;
    unsigned long long* outp = &g_part[b * NCAND + ((seg * 4 + wid) * K1)];
    #pragma unroll
    for (int r = 0; r < K1; r++) {
        unsigned long long m = loc[0];
        #pragma unroll
        for (int o = 16; o; o >>= 1) {
            unsigned long long v = __shfl_xor_sync(0xffffffffu, m, o);
            m = (v > m) ? v : m;
        }
        if (lane == 0) outp[r] = m;
        if (loc[0] == m) {
            #pragma unroll
            for (int j = 0; j < K1 - 1; j++) loc[j] = loc[j + 1];
            loc[K1 - 1] = 0ull;
        }
    }
}

// ---------------------------------------------------------------------------
// Kernel 4b: EXACT rerank of 512 candidates + top-k + softmax.  grid = B.
// Identical per-lane accumulation + shuffle order as the exact score kernel,
// so winning scores are bitwise reproduced.
// ---------------------------------------------------------------------------
__global__ __launch_bounds__(256) void rerank_kernel(
    const int* __restrict__ kptr, const float* __restrict__ W2,
    const float* __restrict__ b2, const float* __restrict__ temp,
    float* __restrict__ out, int N, int B)
{
    __shared__ float qbs[Hc];
    __shared__ float w2s[Hc];
    __shared__ unsigned long long skeys[NCAND];   // 4 KB
    __shared__ unsigned long long warpmax[8];
    __shared__ unsigned long long bestsh;

    int b = blockIdx.x, t = threadIdx.x;
    int k = *kptr; if (k > KMAX) k = KMAX; if (k < 1) k = 1;

    qbs[t] = g_qb[b * Hc + t];
    w2s[t] = W2[t];
    __syncthreads();

    float invt = 1.0f / (fabsf(temp[0]) + 1e-8f);
    float bb = b2[0];
    int w = t >> 5, lane = t & 31;

    float wv[8], qv[8];
    #pragma unroll
    for (int j = 0; j < 8; j++) {
        wv[j] = w2s[lane + 32 * j];
        qv[j] = qbs[lane + 32 * j];
    }

    // warp w handles candidates [w*64, w*64+64)
    const unsigned long long* cands = &g_part[b * NCAND];
    for (int i = 0; i < NCAND / 8; i++) {
        int c = w * (NCAND / 8) + i;
        unsigned long long key = cands[c];
        int idx = (int)(~(unsigned int)(key & 0xffffffffu));
        if (idx < 0) idx = 0; if (idx >= N) idx = N - 1;
        const float* drow = g_da + (size_t)idx * Hc;
        float acc = 0.f;
        #pragma unroll
        for (int j = 0; j < 8; j++) {
            float x = qv[j] + drow[lane + 32 * j];
            acc = fmaf(gelu_f(x), wv[j], acc);
        }
        #pragma unroll
        for (int o = 16; o; o >>= 1)
            acc += __shfl_down_sync(0xffffffffu, acc, o);
        if (lane == 0)
            skeys[c] = pack_key((acc + bb) * invt, idx);
    }
    __syncthreads();

    // top-k over 512 exact keys: thread t owns skeys[t], skeys[t+256]
    unsigned long long m0 = skeys[t], m1 = skeys[t + 256];
    unsigned long long keys[KMAX];
    for (int r = 0; r < k; r++) {
        unsigned long long m = (m0 > m1) ? m0 : m1;
        #pragma unroll
        for (int o = 16; o; o >>= 1) {
            unsigned long long v = __shfl_xor_sync(0xffffffffu, m, o);
            m = (v > m) ? v : m;
        }
        if (lane == 0) warpmax[w] = m;
        __syncthreads();
        if (t == 0) {
            unsigned long long best = 0ull;
            #pragma unroll
            for (int ww = 0; ww < 8; ww++)
                best = (warpmax[ww] > best) ? warpmax[ww] : best;
            bestsh = best;
        }
        __syncthreads();
        unsigned long long best = bestsh;
        if (t == 0) keys[r] = best;
        if (m0 == best) m0 = 0ull;
        if (m1 == best) m1 = 0ull;
        __syncthreads();
    }

    if (t == 0) {
        float gv[KMAX]; int gi[KMAX];
        for (int r = 0; r < k; r++) {
            unsigned int hi = (unsigned int)(keys[r] >> 32);
            unsigned int u = (hi & 0x80000000u) ? (hi ^ 0x80000000u) : ~hi;
            gv[r] = __uint_as_float(u);
            gi[r] = (int)(~(unsigned int)(keys[r] & 0xffffffffu));
        }
        float mx = gv[0], sum = 0.f, ex[KMAX];
        for (int j = 0; j < k; j++) { ex[j] = expf(gv[j] - mx); sum += ex[j]; }
        float inv = 1.0f / sum;
        for (int j = 0; j < k; j++) {
            out[b * k + j] = (float)gi[j];            // top_idx (as float)
            out[B * k + b * k + j] = ex[j] * inv;     // probs
        }
    }
}

// ---------------------------------------------------------------------------
extern "C" void kernel_launch(void* const* d_in, const int* in_sizes, int n_in,
                              void* d_out, int out_size)
{
    const float* query = (const float*)d_in[0];
    const float* docs  = (const float*)d_in[1];
    const int*   kptr  = (const int*)d_in[2];
    const float* Wq    = (const float*)d_in[3];
    const float* bq    = (const float*)d_in[4];
    const float* lnqw  = (const float*)d_in[5];
    const float* lnqb  = (const float*)d_in[6];
    const float* Wd    = (const float*)d_in[7];
    const float* bd    = (const float*)d_in[8];
    const float* lndw  = (const float*)d_in[9];
    const float* lndb  = (const float*)d_in[10];
    const float* W1    = (const float*)d_in[11];
    const float* b1    = (const float*)d_in[12];
    const float* W2    = (const float*)d_in[13];
    const float* b2    = (const float*)d_in[14];
    const float* temp  = (const float*)d_in[15];

    int H = in_sizes[4];            // 256
    int Z = in_sizes[3] / H;        // 512
    int B = in_sizes[0] / Z;        // 32
    int N = in_sizes[1] / Z;        // 20000

    query_kernel<<<B, 256>>>(query, Wq, bq, lnqw, lnqb, W1, b1);
    doc_kernel<<<(N + DPB - 1) / DPB, 256>>>(docs, Wd, bd, lndw, lndb, W1, N);
    score_kernel<<<N / SDOCS, 256>>>(W2, b2, temp, N);
    dim3 g1(SEG, B);
    topk_stage1<<<g1, 128>>>(N);
    rerank_kernel<<<B, 256>>>(kptr, W2, b2, temp, (float*)d_out, N, B);
}

// round 16
// speedup vs baseline: 1.2629x; 1.2629x over previous
#include <cuda_runtime.h>
#include <math.h>

// Problem constants (fixed shapes for this problem instance)
#define Zc 512
#define Hc 256
#define NMAX 20000
#define BMAX 32
#define DPB 32     // docs per block in tensor-core doc kernel
#define SDOCS 8    // docs per block in score kernel
#define KMAX 8     // final output k bound
#define K1 8       // per-warp candidate depth in stage1
#define SEG 16     // stage-1 segments per query (x4 warps = 64 slices)
#define NCAND (SEG * 4 * K1)   // 512 candidates per query

#define XS_STRIDE 516          // 512 + 4 pad (stride%32==4 -> conflict-free)
#define DT_STRIDE 260          // 256 + 4 pad
#define DOC_SMEM_BYTES ((DPB * XS_STRIDE + DPB * DT_STRIDE) * 4)  // 99328

// Scratch (no allocations allowed anywhere)
__device__ float g_qb[BMAX * Hc];                 // qa + b1, [B,H]
__device__ float g_da[(size_t)NMAX * Hc];         // d_t @ W1[H:], [N,H]
__device__ float g_scores[(size_t)BMAX * NMAX];   // APPROX scaled scores [B,N]
__device__ unsigned long long g_part[BMAX * NCAND]; // stage-1 candidate keys

__device__ __forceinline__ float gelu_f(float x) {
    // exact gelu: 0.5*x*(1+erf(x/sqrt(2)))
    return 0.5f * x * (1.0f + erff(x * 0.70710678118654752440f));
}

// fast approximate gelu core WITHOUT the 0.5 factor (folded into weights):
__device__ __forceinline__ float gelu_a2(float x) {
    float x2 = x * x;
    float inner = x * fmaf(0.035677408136f, x2, 0.7978845608028654f);
    float th;
    asm("tanh.approx.f32 %0, %1;" : "=f"(th) : "f"(inner));
    return x * (1.0f + th);
}

// ---- TF32 helpers -----------------------------------------------------------
__device__ __forceinline__ unsigned f2tf(float f) {
    unsigned r; asm("cvt.rna.tf32.f32 %0, %1;" : "=r"(r) : "f"(f)); return r;
}
__device__ __forceinline__ void split_tf(float x, unsigned &hi, unsigned &lo) {
    hi = f2tf(x);
    lo = f2tf(x - __uint_as_float(hi));
}
__device__ __forceinline__ void mma8(float c[4],
    unsigned a0, unsigned a1, unsigned a2, unsigned a3,
    unsigned b0, unsigned b1)
{
    asm volatile(
        "mma.sync.aligned.m16n8k8.row.col.f32.tf32.tf32.f32 "
        "{%0,%1,%2,%3},{%4,%5,%6,%7},{%8,%9},{%0,%1,%2,%3};"
        : "+f"(c[0]), "+f"(c[1]), "+f"(c[2]), "+f"(c[3])
        : "r"(a0), "r"(a1), "r"(a2), "r"(a3), "r"(b0), "r"(b1));
}

// ---------------------------------------------------------------------------
// Kernel 1: query path.  grid = B, block = 256 (one thread per h)
// ---------------------------------------------------------------------------
__global__ __launch_bounds__(256) void query_kernel(
    const float* __restrict__ q, const float* __restrict__ Wq,
    const float* __restrict__ bq, const float* __restrict__ lnw,
    const float* __restrict__ lnb, const float* __restrict__ W1,
    const float* __restrict__ b1)
{
    __shared__ float xq[Zc];
    __shared__ float qt[Hc];
    __shared__ float red[18];
    int b = blockIdx.x, t = threadIdx.x;
    const float* row = q + (size_t)b * Zc;
    for (int i = t; i < Zc; i += 256) xq[i] = row[i];
    __syncthreads();

    float acc = bq[t];
    #pragma unroll 8
    for (int z = 0; z < Zc; z++) acc = fmaf(xq[z], Wq[z * Hc + t], acc);
    float g = gelu_f(acc);

    float s = g, s2 = g * g;
    #pragma unroll
    for (int o = 16; o; o >>= 1) {
        s  += __shfl_down_sync(0xffffffffu, s, o);
        s2 += __shfl_down_sync(0xffffffffu, s2, o);
    }
    if ((t & 31) == 0) { red[t >> 5] = s; red[8 + (t >> 5)] = s2; }
    __syncthreads();
    if (t == 0) {
        float S = 0.f, S2 = 0.f;
        for (int w = 0; w < 8; w++) { S += red[w]; S2 += red[8 + w]; }
        float mu = S / (float)Hc;
        red[16] = mu;
        red[17] = S2 / (float)Hc - mu * mu;
    }
    __syncthreads();
    float mu = red[16], var = red[17];
    float v = (g - mu) * rsqrtf(var + 1e-5f) * lnw[t] + lnb[t];
    qt[t] = v;
    __syncthreads();

    float a2 = b1[t];  // fold b1 here
    #pragma unroll 8
    for (int j = 0; j < Hc; j++) a2 = fmaf(qt[j], W1[j * Hc + t], a2);
    g_qb[b * Hc + t] = a2;
}

// ---------------------------------------------------------------------------
// Kernel 2: doc path — TENSOR CORE (3xTF32) version.
// grid = N/DPB (=625), block = 256 (8 warps), dynamic smem ~97 KB.
// Warp w owns output columns n in [32w, 32w+32); every warp covers all 32 docs
// (2 m16 tiles x 4 n8 subtiles, fp32 accumulators in fragments).
// GEMM precision: 3xTF32 split (hi*hi + hi*lo + lo*hi), ~1e-7 per-term error;
// final rel_err ~1e-5, well within the 1e-3 tolerance.
// ---------------------------------------------------------------------------
__global__ __launch_bounds__(256) void doc_kernel(
    const float* __restrict__ docs, const float* __restrict__ Wd,
    const float* __restrict__ bd, const float* __restrict__ lnw,
    const float* __restrict__ lnb, const float* __restrict__ W1, int N)
{
    extern __shared__ float dsm[];
    float* xs = dsm;                        // [DPB][XS_STRIDE]
    float* dt = dsm + DPB * XS_STRIDE;      // [DPB][DT_STRIDE]

    int t = threadIdx.x, wid = t >> 5, lane = t & 31;
    int grp = lane >> 2, tig = lane & 3;
    int docBase = blockIdx.x * DPB;
    int nb = wid * 32;

    // load doc rows [32][512] into padded smem (f4 stores; 2064B row stride ok)
    for (int i = t; i < DPB * (Zc / 4); i += 256) {
        int row = i >> 7;           // / (Zc/4=128)
        int c4 = i & 127;
        float4 v = ((const float4*)(docs + (size_t)(docBase + row) * Zc))[c4];
        *(float4*)(xs + row * XS_STRIDE + c4 * 4) = v;
    }
    __syncthreads();

    // ---- GEMM1: C[32][256] = xs @ Wd + bd --------------------------------
    float c[2][4][4];
    #pragma unroll
    for (int nt = 0; nt < 4; nt++) {
        float2 bdv = ((const float2*)bd)[(nb + nt * 8) / 2 + tig];
        #pragma unroll
        for (int mt = 0; mt < 2; mt++) {
            c[mt][nt][0] = bdv.x; c[mt][nt][1] = bdv.y;
            c[mt][nt][2] = bdv.x; c[mt][nt][3] = bdv.y;
        }
    }
    for (int kc = 0; kc < Zc / 8; kc++) {
        int k0 = kc * 8;
        unsigned ah[2][4], al[2][4];
        #pragma unroll
        for (int mt = 0; mt < 2; mt++) {
            int r0 = mt * 16 + grp, r1 = r0 + 8;
            split_tf(xs[r0 * XS_STRIDE + k0 + tig],     ah[mt][0], al[mt][0]);
            split_tf(xs[r1 * XS_STRIDE + k0 + tig],     ah[mt][1], al[mt][1]);
            split_tf(xs[r0 * XS_STRIDE + k0 + tig + 4], ah[mt][2], al[mt][2]);
            split_tf(xs[r1 * XS_STRIDE + k0 + tig + 4], ah[mt][3], al[mt][3]);
        }
        #pragma unroll
        for (int nt = 0; nt < 4; nt++) {
            int n0 = nb + nt * 8;
            float b0f = Wd[(size_t)(k0 + tig) * Hc + n0 + grp];
            float b1f = Wd[(size_t)(k0 + tig + 4) * Hc + n0 + grp];
            unsigned bh0, bl0, bh1, bl1;
            split_tf(b0f, bh0, bl0);
            split_tf(b1f, bh1, bl1);
            #pragma unroll
            for (int mt = 0; mt < 2; mt++) {
                mma8(c[mt][nt], ah[mt][0], ah[mt][1], ah[mt][2], ah[mt][3], bh0, bh1);
                mma8(c[mt][nt], ah[mt][0], ah[mt][1], ah[mt][2], ah[mt][3], bl0, bl1);
                mma8(c[mt][nt], al[mt][0], al[mt][1], al[mt][2], al[mt][3], bh0, bh1);
            }
        }
    }
    // gelu -> dt
    #pragma unroll
    for (int mt = 0; mt < 2; mt++) {
        #pragma unroll
        for (int nt = 0; nt < 4; nt++) {
            int r0 = mt * 16 + grp, r1 = r0 + 8;
            int col = nb + nt * 8 + 2 * tig;
            dt[r0 * DT_STRIDE + col]     = gelu_f(c[mt][nt][0]);
            dt[r0 * DT_STRIDE + col + 1] = gelu_f(c[mt][nt][1]);
            dt[r1 * DT_STRIDE + col]     = gelu_f(c[mt][nt][2]);
            dt[r1 * DT_STRIDE + col + 1] = gelu_f(c[mt][nt][3]);
        }
    }
    __syncthreads();

    // ---- LayerNorm per doc: warp wid normalizes docs 4*wid .. 4*wid+3 ----
    #pragma unroll
    for (int dd = 0; dd < 4; dd++) {
        float* r = dt + (wid * 4 + dd) * DT_STRIDE;
        float s = 0.f, s2 = 0.f;
        #pragma unroll
        for (int j = lane; j < Hc; j += 32) { float v = r[j]; s += v; s2 += v * v; }
        #pragma unroll
        for (int o = 16; o; o >>= 1) {
            s  += __shfl_xor_sync(0xffffffffu, s, o);
            s2 += __shfl_xor_sync(0xffffffffu, s2, o);
        }
        float mu = s / (float)Hc;
        float rin = rsqrtf(s2 / (float)Hc - mu * mu + 1e-5f);
        #pragma unroll
        for (int j = lane; j < Hc; j += 32)
            r[j] = (r[j] - mu) * rin * lnw[j] + lnb[j];
    }
    __syncthreads();

    // ---- GEMM2: g_da[32][256] = dt @ W1[H:2H] ----------------------------
    float e[2][4][4];
    #pragma unroll
    for (int mt = 0; mt < 2; mt++)
        #pragma unroll
        for (int nt = 0; nt < 4; nt++)
            #pragma unroll
            for (int i = 0; i < 4; i++) e[mt][nt][i] = 0.f;

    for (int kc = 0; kc < Hc / 8; kc++) {
        int k0 = kc * 8;
        unsigned ah[2][4], al[2][4];
        #pragma unroll
        for (int mt = 0; mt < 2; mt++) {
            int r0 = mt * 16 + grp, r1 = r0 + 8;
            split_tf(dt[r0 * DT_STRIDE + k0 + tig],     ah[mt][0], al[mt][0]);
            split_tf(dt[r1 * DT_STRIDE + k0 + tig],     ah[mt][1], al[mt][1]);
            split_tf(dt[r0 * DT_STRIDE + k0 + tig + 4], ah[mt][2], al[mt][2]);
            split_tf(dt[r1 * DT_STRIDE + k0 + tig + 4], ah[mt][3], al[mt][3]);
        }
        #pragma unroll
        for (int nt = 0; nt < 4; nt++) {
            int n0 = nb + nt * 8;
            float b0f = W1[(size_t)(Hc + k0 + tig) * Hc + n0 + grp];
            float b1f = W1[(size_t)(Hc + k0 + tig + 4) * Hc + n0 + grp];
            unsigned bh0, bl0, bh1, bl1;
            split_tf(b0f, bh0, bl0);
            split_tf(b1f, bh1, bl1);
            #pragma unroll
            for (int mt = 0; mt < 2; mt++) {
                mma8(e[mt][nt], ah[mt][0], ah[mt][1], ah[mt][2], ah[mt][3], bh0, bh1);
                mma8(e[mt][nt], ah[mt][0], ah[mt][1], ah[mt][2], ah[mt][3], bl0, bl1);
                mma8(e[mt][nt], al[mt][0], al[mt][1], al[mt][2], al[mt][3], bh0, bh1);
            }
        }
    }
    #pragma unroll
    for (int mt = 0; mt < 2; mt++) {
        #pragma unroll
        for (int nt = 0; nt < 4; nt++) {
            int r0 = mt * 16 + grp, r1 = r0 + 8;
            int col = nb + nt * 8 + 2 * tig;
            g_da[(size_t)(docBase + r0) * Hc + col]     = e[mt][nt][0];
            g_da[(size_t)(docBase + r0) * Hc + col + 1] = e[mt][nt][1];
            g_da[(size_t)(docBase + r1) * Hc + col]     = e[mt][nt][2];
            g_da[(size_t)(docBase + r1) * Hc + col + 1] = e[mt][nt][3];
        }
    }
}

// ---------------------------------------------------------------------------
// Kernel 3: APPROXIMATE pairwise scoring — proven scalar structure.
// grid = N/SDOCS, block = 256.  0.5 folded into weights (approx path only).
// ---------------------------------------------------------------------------
__global__ __launch_bounds__(256) void score_kernel(
    const float* __restrict__ W2, const float* __restrict__ b2,
    const float* __restrict__ temp, int N)
{
    __shared__ float qbs[BMAX * Hc];   // 32 KB
    __shared__ float das[SDOCS][Hc];   // 8 KB
    __shared__ float w2s[Hc];
    int t = threadIdx.x;

    const float4* qsrc = (const float4*)g_qb;
    float4* qdst = (float4*)qbs;
    #pragma unroll
    for (int i = t; i < BMAX * Hc / 4; i += 256) qdst[i] = qsrc[i];
    w2s[t] = W2[t];
    int docBase = blockIdx.x * SDOCS;
    {
        const float4* dsrc = (const float4*)(g_da + (size_t)docBase * Hc);
        float4* ddst = (float4*)&das[0][0];
        ddst[t] = dsrc[t];
        ddst[t + 256] = dsrc[t + 256];
    }
    __syncthreads();

    float invt = 1.0f / (fabsf(temp[0]) + 1e-8f);
    float bb = b2[0];
    int w = t >> 5, lane = t & 31;

    float wv[8];
    #pragma unroll
    for (int j = 0; j < 8; j++) wv[j] = 0.5f * w2s[lane + 32 * j];

    float qv[4][8];
    #pragma unroll
    for (int bi = 0; bi < 4; bi++) {
        const float* qrow = &qbs[(w + 8 * bi) * Hc];
        #pragma unroll
        for (int j = 0; j < 8; j++) qv[bi][j] = qrow[lane + 32 * j];
    }

    #pragma unroll
    for (int d = 0; d < SDOCS; d++) {
        float dv[8];
        #pragma unroll
        for (int j = 0; j < 8; j++) dv[j] = das[d][lane + 32 * j];
        float acc0 = 0.f, acc1 = 0.f, acc2 = 0.f, acc3 = 0.f;
        #pragma unroll
        for (int j = 0; j < 8; j++) {
            float wj = wv[j], dj = dv[j];
            acc0 = fmaf(gelu_a2(qv[0][j] + dj), wj, acc0);
            acc1 = fmaf(gelu_a2(qv[1][j] + dj), wj, acc1);
            acc2 = fmaf(gelu_a2(qv[2][j] + dj), wj, acc2);
            acc3 = fmaf(gelu_a2(qv[3][j] + dj), wj, acc3);
        }
        #pragma unroll
        for (int o = 16; o; o >>= 1) {
            acc0 += __shfl_down_sync(0xffffffffu, acc0, o);
            acc1 += __shfl_down_sync(0xffffffffu, acc1, o);
            acc2 += __shfl_down_sync(0xffffffffu, acc2, o);
            acc3 += __shfl_down_sync(0xffffffffu, acc3, o);
        }
        if (lane == 0) {
            g_scores[(size_t)(w +  0) * N + docBase + d] = (acc0 + bb) * invt;
            g_scores[(size_t)(w +  8) * N + docBase + d] = (acc1 + bb) * invt;
            g_scores[(size_t)(w + 16) * N + docBase + d] = (acc2 + bb) * invt;
            g_scores[(size_t)(w + 24) * N + docBase + d] = (acc3 + bb) * invt;
        }
    }
}

// ---------------------------------------------------------------------------
// Top-k keys: (score, index) packed into one orderable uint64.
// ---------------------------------------------------------------------------
__device__ __forceinline__ unsigned long long pack_key(float s, int i) {
    unsigned int u = __float_as_uint(s);
    u = (u & 0x80000000u) ? ~u : (u | 0x80000000u);
    return ((unsigned long long)u << 32) | (unsigned int)(~(unsigned int)i);
}

// ---------------------------------------------------------------------------
// Kernel 4a: per-warp top-8 candidates (approx scores). grid=(SEG,B), b=128.
// ---------------------------------------------------------------------------
__global__ __launch_bounds__(128) void topk_stage1(int N)
{
    int seg = blockIdx.x, b = blockIdx.y, t = threadIdx.x;
    int nseg = gridDim.x;
    int seglen = (N + nseg - 1) / nseg;
    int start = seg * seglen;
    int end = start + seglen; if (end > N) end = N;

    unsigned long long loc[K1];
    #pragma unroll
    for (int j = 0; j < K1; j++) loc[j] = 0ull;

    const float* row = g_scores + (size_t)b * N;
    for (int i = start + t; i < end; i += 128) {
        unsigned long long key = pack_key(row[i], i);
        if (key > loc[K1 - 1]) {
            #pragma unroll
            for (int j = 0; j < K1; j++) {
                unsigned long long cur = loc[j];
                bool gt = key > cur;
                loc[j] = gt ? key : cur;
                key    = gt ? cur : key;
            }
        }
    }

    int wid = t >> 5, lane = t & 31;
    unsigned long long* outp = &g_part[b * NCAND + ((seg * 4 + wid) * K1)];
    #pragma unroll
    for (int r = 0; r < K1; r++) {
        unsigned long long m = loc[0];
        #pragma unroll
        for (int o = 16; o; o >>= 1) {
            unsigned long long v = __shfl_xor_sync(0xffffffffu, m, o);
            m = (v > m) ? v : m;
        }
        if (lane == 0) outp[r] = m;
        if (loc[0] == m) {
            #pragma unroll
            for (int j = 0; j < K1 - 1; j++) loc[j] = loc[j + 1];
            loc[K1 - 1] = 0ull;
        }
    }
}

// ---------------------------------------------------------------------------
// Kernel 4b: EXACT rerank of 512 candidates + top-k + softmax.  grid = B.
// ---------------------------------------------------------------------------
__global__ __launch_bounds__(256) void rerank_kernel(
    const int* __restrict__ kptr, const float* __restrict__ W2,
    const float* __restrict__ b2, const float* __restrict__ temp,
    float* __restrict__ out, int N, int B)
{
    __shared__ float qbs[Hc];
    __shared__ float w2s[Hc];
    __shared__ unsigned long long skeys[NCAND];   // 4 KB
    __shared__ unsigned long long warpmax[8];
    __shared__ unsigned long long bestsh;

    int b = blockIdx.x, t = threadIdx.x;
    int k = *kptr; if (k > KMAX) k = KMAX; if (k < 1) k = 1;

    qbs[t] = g_qb[b * Hc + t];
    w2s[t] = W2[t];
    __syncthreads();

    float invt = 1.0f / (fabsf(temp[0]) + 1e-8f);
    float bb = b2[0];
    int w = t >> 5, lane = t & 31;

    float wv[8], qv[8];
    #pragma unroll
    for (int j = 0; j < 8; j++) {
        wv[j] = w2s[lane + 32 * j];
        qv[j] = qbs[lane + 32 * j];
    }

    const unsigned long long* cands = &g_part[b * NCAND];
    for (int i = 0; i < NCAND / 8; i++) {
        int c = w * (NCAND / 8) + i;
        unsigned long long key = cands[c];
        int idx = (int)(~(unsigned int)(key & 0xffffffffu));
        if (idx < 0) idx = 0; if (idx >= N) idx = N - 1;
        const float* drow = g_da + (size_t)idx * Hc;
        float acc = 0.f;
        #pragma unroll
        for (int j = 0; j < 8; j++) {
            float x = qv[j] + drow[lane + 32 * j];
            acc = fmaf(gelu_f(x), wv[j], acc);
        }
        #pragma unroll
        for (int o = 16; o; o >>= 1)
            acc += __shfl_down_sync(0xffffffffu, acc, o);
        if (lane == 0)
            skeys[c] = pack_key((acc + bb) * invt, idx);
    }
    __syncthreads();

    unsigned long long m0 = skeys[t], m1 = skeys[t + 256];
    unsigned long long keys[KMAX];
    for (int r = 0; r < k; r++) {
        unsigned long long m = (m0 > m1) ? m0 : m1;
        #pragma unroll
        for (int o = 16; o; o >>= 1) {
            unsigned long long v = __shfl_xor_sync(0xffffffffu, m, o);
            m = (v > m) ? v : m;
        }
        if (lane == 0) warpmax[w] = m;
        __syncthreads();
        if (t == 0) {
            unsigned long long best = 0ull;
            #pragma unroll
            for (int ww = 0; ww < 8; ww++)
                best = (warpmax[ww] > best) ? warpmax[ww] : best;
            bestsh = best;
        }
        __syncthreads();
        unsigned long long best = bestsh;
        if (t == 0) keys[r] = best;
        if (m0 == best) m0 = 0ull;
        if (m1 == best) m1 = 0ull;
        __syncthreads();
    }

    if (t == 0) {
        float gv[KMAX]; int gi[KMAX];
        for (int r = 0; r < k; r++) {
            unsigned int hi = (unsigned int)(keys[r] >> 32);
            unsigned int u = (hi & 0x80000000u) ? (hi ^ 0x80000000u) : ~hi;
            gv[r] = __uint_as_float(u);
            gi[r] = (int)(~(unsigned int)(keys[r] & 0xffffffffu));
        }
        float mx = gv[0], sum = 0.f, ex[KMAX];
        for (int j = 0; j < k; j++) { ex[j] = expf(gv[j] - mx); sum += ex[j]; }
        float inv = 1.0f / sum;
        for (int j = 0; j < k; j++) {
            out[b * k + j] = (float)gi[j];            // top_idx (as float)
            out[B * k + b * k + j] = ex[j] * inv;     // probs
        }
    }
}

// ---------------------------------------------------------------------------
extern "C" void kernel_launch(void* const* d_in, const int* in_sizes, int n_in,
                              void* d_out, int out_size)
{
    const float* query = (const float*)d_in[0];
    const float* docs  = (const float*)d_in[1];
    const int*   kptr  = (const int*)d_in[2];
    const float* Wq    = (const float*)d_in[3];
    const float* bq    = (const float*)d_in[4];
    const float* lnqw  = (const float*)d_in[5];
    const float* lnqb  = (const float*)d_in[6];
    const float* Wd    = (const float*)d_in[7];
    const float* bd    = (const float*)d_in[8];
    const float* lndw  = (const float*)d_in[9];
    const float* lndb  = (const float*)d_in[10];
    const float* W1    = (const float*)d_in[11];
    const float* b1    = (const float*)d_in[12];
    const float* W2    = (const float*)d_in[13];
    const float* b2    = (const float*)d_in[14];
    const float* temp  = (const float*)d_in[15];

    int H = in_sizes[4];            // 256
    int Z = in_sizes[3] / H;        // 512
    int B = in_sizes[0] / Z;        // 32
    int N = in_sizes[1] / Z;        // 20000

    // opt-in to >48KB dynamic smem for the tensor doc kernel (attribute
    // setter: not a stream op / alloc / sync — legal under graph capture)
    cudaFuncSetAttribute(doc_kernel,
                         cudaFuncAttributeMaxDynamicSharedMemorySize,
                         DOC_SMEM_BYTES);

    query_kernel<<<B, 256>>>(query, Wq, bq, lnqw, lnqb, W1, b1);
    doc_kernel<<<(N + DPB - 1) / DPB, 256, DOC_SMEM_BYTES>>>(
        docs, Wd, bd, lndw, lndb, W1, N);
    score_kernel<<<N / SDOCS, 256>>>(W2, b2, temp, N);
    dim3 g1(SEG, B);
    topk_stage1<<<g1, 128>>>(N);
    rerank_kernel<<<B, 256>>>(kptr, W2, b2, temp, (float*)d_out, N, B);
}

// round 17
// speedup vs baseline: 1.2848x; 1.0173x over previous
#include <cuda_runtime.h>
#include <cuda_fp16.h>
#include <math.h>

// Problem constants (fixed shapes for this problem instance)
#define Zc 512
#define Hc 256
#define NMAX 20000
#define BMAX 32
#define DPB 32     // docs per block in tensor-core doc kernel
#define SDOCS 8    // docs per block in score kernel
#define KMAX 8     // final output k bound
#define K1 8       // per-warp candidate depth in stage1
#define SEG 16     // stage-1 segments per query (x4 warps = 64 slices)
#define NCAND (SEG * 4 * K1)   // 512 candidates per query

#define XS_STRIDE 516          // 512 + 4 pad (stride%32==4 -> conflict-free)
#define DT_STRIDE 260          // 256 + 4 pad
#define DOC_SMEM_BYTES ((DPB * XS_STRIDE + DPB * DT_STRIDE) * 4)  // 99328

// Scratch (no allocations allowed anywhere)
__device__ float g_qb[BMAX * Hc];                 // qa + b1, [B,H]
__device__ float g_da[(size_t)NMAX * Hc];         // d_t @ W1[H:], [N,H]
__device__ float g_scores[(size_t)BMAX * NMAX];   // APPROX scaled scores [B,N]
__device__ unsigned long long g_part[BMAX * NCAND]; // stage-1 candidate keys

__device__ __forceinline__ float gelu_f(float x) {
    // exact gelu: 0.5*x*(1+erf(x/sqrt(2)))
    return 0.5f * x * (1.0f + erff(x * 0.70710678118654752440f));
}

// ---- TF32 helpers -----------------------------------------------------------
__device__ __forceinline__ unsigned f2tf(float f) {
    unsigned r; asm("cvt.rna.tf32.f32 %0, %1;" : "=r"(r) : "f"(f)); return r;
}
__device__ __forceinline__ void split_tf(float x, unsigned &hi, unsigned &lo) {
    hi = f2tf(x);
    lo = f2tf(x - __uint_as_float(hi));
}
__device__ __forceinline__ void mma8(float c[4],
    unsigned a0, unsigned a1, unsigned a2, unsigned a3,
    unsigned b0, unsigned b1)
{
    asm volatile(
        "mma.sync.aligned.m16n8k8.row.col.f32.tf32.tf32.f32 "
        "{%0,%1,%2,%3},{%4,%5,%6,%7},{%8,%9},{%0,%1,%2,%3};"
        : "+f"(c[0]), "+f"(c[1]), "+f"(c[2]), "+f"(c[3])
        : "r"(a0), "r"(a1), "r"(a2), "r"(a3), "r"(b0), "r"(b1));
}

// ---- half2 helpers (approx score pass only) --------------------------------
__device__ __forceinline__ __half2 h2tanh_ap(__half2 x) {
    unsigned r, xi = *(unsigned*)&x;
    asm("tanh.approx.f16x2 %0, %1;" : "=r"(r) : "r"(xi));
    return *(__half2*)&r;
}

// ---------------------------------------------------------------------------
// Kernel 1: query path.  grid = B, block = 256 (one thread per h)
// ---------------------------------------------------------------------------
__global__ __launch_bounds__(256) void query_kernel(
    const float* __restrict__ q, const float* __restrict__ Wq,
    const float* __restrict__ bq, const float* __restrict__ lnw,
    const float* __restrict__ lnb, const float* __restrict__ W1,
    const float* __restrict__ b1)
{
    __shared__ float xq[Zc];
    __shared__ float qt[Hc];
    __shared__ float red[18];
    int b = blockIdx.x, t = threadIdx.x;
    const float* row = q + (size_t)b * Zc;
    for (int i = t; i < Zc; i += 256) xq[i] = row[i];
    __syncthreads();

    float acc = bq[t];
    #pragma unroll 8
    for (int z = 0; z < Zc; z++) acc = fmaf(xq[z], Wq[z * Hc + t], acc);
    float g = gelu_f(acc);

    float s = g, s2 = g * g;
    #pragma unroll
    for (int o = 16; o; o >>= 1) {
        s  += __shfl_down_sync(0xffffffffu, s, o);
        s2 += __shfl_down_sync(0xffffffffu, s2, o);
    }
    if ((t & 31) == 0) { red[t >> 5] = s; red[8 + (t >> 5)] = s2; }
    __syncthreads();
    if (t == 0) {
        float S = 0.f, S2 = 0.f;
        for (int w = 0; w < 8; w++) { S += red[w]; S2 += red[8 + w]; }
        float mu = S / (float)Hc;
        red[16] = mu;
        red[17] = S2 / (float)Hc - mu * mu;
    }
    __syncthreads();
    float mu = red[16], var = red[17];
    float v = (g - mu) * rsqrtf(var + 1e-5f) * lnw[t] + lnb[t];
    qt[t] = v;
    __syncthreads();

    float a2 = b1[t];  // fold b1 here
    #pragma unroll 8
    for (int j = 0; j < Hc; j++) a2 = fmaf(qt[j], W1[j * Hc + t], a2);
    g_qb[b * Hc + t] = a2;
}

// ---------------------------------------------------------------------------
// Kernel 2: doc path — TENSOR CORE (3xTF32), unchanged from the 365us run.
// ---------------------------------------------------------------------------
__global__ __launch_bounds__(256) void doc_kernel(
    const float* __restrict__ docs, const float* __restrict__ Wd,
    const float* __restrict__ bd, const float* __restrict__ lnw,
    const float* __restrict__ lnb, const float* __restrict__ W1, int N)
{
    extern __shared__ float dsm[];
    float* xs = dsm;                        // [DPB][XS_STRIDE]
    float* dt = dsm + DPB * XS_STRIDE;      // [DPB][DT_STRIDE]

    int t = threadIdx.x, wid = t >> 5, lane = t & 31;
    int grp = lane >> 2, tig = lane & 3;
    int docBase = blockIdx.x * DPB;
    int nb = wid * 32;

    for (int i = t; i < DPB * (Zc / 4); i += 256) {
        int row = i >> 7;
        int c4 = i & 127;
        float4 v = ((const float4*)(docs + (size_t)(docBase + row) * Zc))[c4];
        *(float4*)(xs + row * XS_STRIDE + c4 * 4) = v;
    }
    __syncthreads();

    // ---- GEMM1: C[32][256] = xs @ Wd + bd --------------------------------
    float c[2][4][4];
    #pragma unroll
    for (int nt = 0; nt < 4; nt++) {
        float2 bdv = ((const float2*)bd)[(nb + nt * 8) / 2 + tig];
        #pragma unroll
        for (int mt = 0; mt < 2; mt++) {
            c[mt][nt][0] = bdv.x; c[mt][nt][1] = bdv.y;
            c[mt][nt][2] = bdv.x; c[mt][nt][3] = bdv.y;
        }
    }
    for (int kc = 0; kc < Zc / 8; kc++) {
        int k0 = kc * 8;
        unsigned ah[2][4], al[2][4];
        #pragma unroll
        for (int mt = 0; mt < 2; mt++) {
            int r0 = mt * 16 + grp, r1 = r0 + 8;
            split_tf(xs[r0 * XS_STRIDE + k0 + tig],     ah[mt][0], al[mt][0]);
            split_tf(xs[r1 * XS_STRIDE + k0 + tig],     ah[mt][1], al[mt][1]);
            split_tf(xs[r0 * XS_STRIDE + k0 + tig + 4], ah[mt][2], al[mt][2]);
            split_tf(xs[r1 * XS_STRIDE + k0 + tig + 4], ah[mt][3], al[mt][3]);
        }
        #pragma unroll
        for (int nt = 0; nt < 4; nt++) {
            int n0 = nb + nt * 8;
            float b0f = Wd[(size_t)(k0 + tig) * Hc + n0 + grp];
            float b1f = Wd[(size_t)(k0 + tig + 4) * Hc + n0 + grp];
            unsigned bh0, bl0, bh1, bl1;
            split_tf(b0f, bh0, bl0);
            split_tf(b1f, bh1, bl1);
            #pragma unroll
            for (int mt = 0; mt < 2; mt++) {
                mma8(c[mt][nt], ah[mt][0], ah[mt][1], ah[mt][2], ah[mt][3], bh0, bh1);
                mma8(c[mt][nt], ah[mt][0], ah[mt][1], ah[mt][2], ah[mt][3], bl0, bl1);
                mma8(c[mt][nt], al[mt][0], al[mt][1], al[mt][2], al[mt][3], bh0, bh1);
            }
        }
    }
    #pragma unroll
    for (int mt = 0; mt < 2; mt++) {
        #pragma unroll
        for (int nt = 0; nt < 4; nt++) {
            int r0 = mt * 16 + grp, r1 = r0 + 8;
            int col = nb + nt * 8 + 2 * tig;
            dt[r0 * DT_STRIDE + col]     = gelu_f(c[mt][nt][0]);
            dt[r0 * DT_STRIDE + col + 1] = gelu_f(c[mt][nt][1]);
            dt[r1 * DT_STRIDE + col]     = gelu_f(c[mt][nt][2]);
            dt[r1 * DT_STRIDE + col + 1] = gelu_f(c[mt][nt][3]);
        }
    }
    __syncthreads();

    // ---- LayerNorm per doc: warp wid normalizes docs 4*wid .. 4*wid+3 ----
    #pragma unroll
    for (int dd = 0; dd < 4; dd++) {
        float* r = dt + (wid * 4 + dd) * DT_STRIDE;
        float s = 0.f, s2 = 0.f;
        #pragma unroll
        for (int j = lane; j < Hc; j += 32) { float v = r[j]; s += v; s2 += v * v; }
        #pragma unroll
        for (int o = 16; o; o >>= 1) {
            s  += __shfl_xor_sync(0xffffffffu, s, o);
            s2 += __shfl_xor_sync(0xffffffffu, s2, o);
        }
        float mu = s / (float)Hc;
        float rin = rsqrtf(s2 / (float)Hc - mu * mu + 1e-5f);
        #pragma unroll
        for (int j = lane; j < Hc; j += 32)
            r[j] = (r[j] - mu) * rin * lnw[j] + lnb[j];
    }
    __syncthreads();

    // ---- GEMM2: g_da[32][256] = dt @ W1[H:2H] ----------------------------
    float e[2][4][4];
    #pragma unroll
    for (int mt = 0; mt < 2; mt++)
        #pragma unroll
        for (int nt = 0; nt < 4; nt++)
            #pragma unroll
            for (int i = 0; i < 4; i++) e[mt][nt][i] = 0.f;

    for (int kc = 0; kc < Hc / 8; kc++) {
        int k0 = kc * 8;
        unsigned ah[2][4], al[2][4];
        #pragma unroll
        for (int mt = 0; mt < 2; mt++) {
            int r0 = mt * 16 + grp, r1 = r0 + 8;
            split_tf(dt[r0 * DT_STRIDE + k0 + tig],     ah[mt][0], al[mt][0]);
            split_tf(dt[r1 * DT_STRIDE + k0 + tig],     ah[mt][1], al[mt][1]);
            split_tf(dt[r0 * DT_STRIDE + k0 + tig + 4], ah[mt][2], al[mt][2]);
            split_tf(dt[r1 * DT_STRIDE + k0 + tig + 4], ah[mt][3], al[mt][3]);
        }
        #pragma unroll
        for (int nt = 0; nt < 4; nt++) {
            int n0 = nb + nt * 8;
            float b0f = W1[(size_t)(Hc + k0 + tig) * Hc + n0 + grp];
            float b1f = W1[(size_t)(Hc + k0 + tig + 4) * Hc + n0 + grp];
            unsigned bh0, bl0, bh1, bl1;
            split_tf(b0f, bh0, bl0);
            split_tf(b1f, bh1, bl1);
            #pragma unroll
            for (int mt = 0; mt < 2; mt++) {
                mma8(e[mt][nt], ah[mt][0], ah[mt][1], ah[mt][2], ah[mt][3], bh0, bh1);
                mma8(e[mt][nt], ah[mt][0], ah[mt][1], ah[mt][2], ah[mt][3], bl0, bl1);
                mma8(e[mt][nt], al[mt][0], al[mt][1], al[mt][2], al[mt][3], bh0, bh1);
            }
        }
    }
    #pragma unroll
    for (int mt = 0; mt < 2; mt++) {
        #pragma unroll
        for (int nt = 0; nt < 4; nt++) {
            int r0 = mt * 16 + grp, r1 = r0 + 8;
            int col = nb + nt * 8 + 2 * tig;
            g_da[(size_t)(docBase + r0) * Hc + col]     = e[mt][nt][0];
            g_da[(size_t)(docBase + r0) * Hc + col + 1] = e[mt][nt][1];
            g_da[(size_t)(docBase + r1) * Hc + col]     = e[mt][nt][2];
            g_da[(size_t)(docBase + r1) * Hc + col + 1] = e[mt][nt][3];
        }
    }
}

// ---------------------------------------------------------------------------
// Kernel 3: APPROXIMATE pairwise scoring — HALF2 (2 elements/instr).
// grid = N/SDOCS, block = 256.  Per-lane half accumulation is only 4 HFMA2
// deep; cross-lane reduction in fp32.  Candidates only; winners re-scored
// exactly in rerank -> final rel_err unchanged.
// Lane owns h-pairs p = lane+32*j2 (j2=0..3), i.e. h = 2p, 2p+1.
// ---------------------------------------------------------------------------
__global__ __launch_bounds__(256) void score_kernel(
    const float* __restrict__ W2, const float* __restrict__ b2,
    const float* __restrict__ temp, int N)
{
    __shared__ __half2 qh2[BMAX * Hc / 2];    // 16 KB
    __shared__ __half2 dh2[SDOCS * Hc / 2];   // 4 KB
    __shared__ __half2 wh2[Hc / 2];           // 0.5 KB
    int t = threadIdx.x;

    for (int i = t; i < BMAX * Hc / 2; i += 256) {
        float2 v = ((const float2*)g_qb)[i];
        qh2[i] = __floats2half2_rn(v.x, v.y);
    }
    if (t < Hc / 2) {
        float2 v = ((const float2*)W2)[t];
        wh2[t] = __floats2half2_rn(0.5f * v.x, 0.5f * v.y);
    }
    int docBase = blockIdx.x * SDOCS;
    for (int i = t; i < SDOCS * Hc / 2; i += 256) {
        float2 v = ((const float2*)(g_da + (size_t)docBase * Hc))[i];
        dh2[i] = __floats2half2_rn(v.x, v.y);
    }
    __syncthreads();

    float invt = 1.0f / (fabsf(temp[0]) + 1e-8f);
    float bb = b2[0];
    int w = t >> 5, lane = t & 31;

    const __half2 c35 = __float2half2_rn(0.035677408136f);
    const __half2 c79 = __float2half2_rn(0.7978845608028654f);

    __half2 wv[4];
    #pragma unroll
    for (int j = 0; j < 4; j++) wv[j] = wh2[lane + 32 * j];

    __half2 qv[4][4];
    #pragma unroll
    for (int bi = 0; bi < 4; bi++)
        #pragma unroll
        for (int j = 0; j < 4; j++)
            qv[bi][j] = qh2[(w + 8 * bi) * (Hc / 2) + lane + 32 * j];

    #pragma unroll
    for (int d = 0; d < SDOCS; d++) {
        __half2 dv[4];
        #pragma unroll
        for (int j = 0; j < 4; j++) dv[j] = dh2[d * (Hc / 2) + lane + 32 * j];
        __half2 a0 = __float2half2_rn(0.f), a1 = a0, a2 = a0, a3 = a0;
        #pragma unroll
        for (int j = 0; j < 4; j++) {
            __half2 wj = wv[j], dj = dv[j];
            {
                __half2 x = __hadd2(qv[0][j], dj);
                __half2 inner = __hmul2(x, __hfma2(c35, __hmul2(x, x), c79));
                a0 = __hfma2(__hfma2(x, h2tanh_ap(inner), x), wj, a0);
            }
            {
                __half2 x = __hadd2(qv[1][j], dj);
                __half2 inner = __hmul2(x, __hfma2(c35, __hmul2(x, x), c79));
                a1 = __hfma2(__hfma2(x, h2tanh_ap(inner), x), wj, a1);
            }
            {
                __half2 x = __hadd2(qv[2][j], dj);
                __half2 inner = __hmul2(x, __hfma2(c35, __hmul2(x, x), c79));
                a2 = __hfma2(__hfma2(x, h2tanh_ap(inner), x), wj, a2);
            }
            {
                __half2 x = __hadd2(qv[3][j], dj);
                __half2 inner = __hmul2(x, __hfma2(c35, __hmul2(x, x), c79));
                a3 = __hfma2(__hfma2(x, h2tanh_ap(inner), x), wj, a3);
            }
        }
        // convert to fp32, reduce across lanes in fp32
        float acc0 = __low2float(a0) + __high2float(a0);
        float acc1 = __low2float(a1) + __high2float(a1);
        float acc2 = __low2float(a2) + __high2float(a2);
        float acc3 = __low2float(a3) + __high2float(a3);
        #pragma unroll
        for (int o = 16; o; o >>= 1) {
            acc0 += __shfl_down_sync(0xffffffffu, acc0, o);
            acc1 += __shfl_down_sync(0xffffffffu, acc1, o);
            acc2 += __shfl_down_sync(0xffffffffu, acc2, o);
            acc3 += __shfl_down_sync(0xffffffffu, acc3, o);
        }
        if (lane == 0) {
            g_scores[(size_t)(w +  0) * N + docBase + d] = (acc0 + bb) * invt;
            g_scores[(size_t)(w +  8) * N + docBase + d] = (acc1 + bb) * invt;
            g_scores[(size_t)(w + 16) * N + docBase + d] = (acc2 + bb) * invt;
            g_scores[(size_t)(w + 24) * N + docBase + d] = (acc3 + bb) * invt;
        }
    }
}

// ---------------------------------------------------------------------------
// Top-k keys: (score, index) packed into one orderable uint64.
// ---------------------------------------------------------------------------
__device__ __forceinline__ unsigned long long pack_key(float s, int i) {
    unsigned int u = __float_as_uint(s);
    u = (u & 0x80000000u) ? ~u : (u | 0x80000000u);
    return ((unsigned long long)u << 32) | (unsigned int)(~(unsigned int)i);
}

// ---------------------------------------------------------------------------
// Kernel 4a: per-warp top-8 candidates (approx scores). grid=(SEG,B), b=128.
// ---------------------------------------------------------------------------
__global__ __launch_bounds__(128) void topk_stage1(int N)
{
    int seg = blockIdx.x, b = blockIdx.y, t = threadIdx.x;
    int nseg = gridDim.x;
    int seglen = (N + nseg - 1) / nseg;
    int start = seg * seglen;
    int end = start + seglen; if (end > N) end = N;

    unsigned long long loc[K1];
    #pragma unroll
    for (int j = 0; j < K1; j++) loc[j] = 0ull;

    const float* row = g_scores + (size_t)b * N;
    for (int i = start + t; i < end; i += 128) {
        unsigned long long key = pack_key(row[i], i);
        if (key > loc[K1 - 1]) {
            #pragma unroll
            for (int j = 0; j < K1; j++) {
                unsigned long long cur = loc[j];
                bool gt = key > cur;
                loc[j] = gt ? key : cur;
                key    = gt ? cur : key;
            }
        }
    }

    int wid = t >> 5, lane = t & 31;
    unsigned long long* outp = &g_part[b * NCAND + ((seg * 4 + wid) * K1)];
    #pragma unroll
    for (int r = 0; r < K1; r++) {
        unsigned long long m = loc[0];
        #pragma unroll
        for (int o = 16; o; o >>= 1) {
            unsigned long long v = __shfl_xor_sync(0xffffffffu, m, o);
            m = (v > m) ? v : m;
        }
        if (lane == 0) outp[r] = m;
        if (loc[0] == m) {
            #pragma unroll
            for (int j = 0; j < K1 - 1; j++) loc[j] = loc[j + 1];
            loc[K1 - 1] = 0ull;
        }
    }
}

// ---------------------------------------------------------------------------
// Kernel 4b: EXACT rerank of 512 candidates + top-k + softmax.  grid = B.
// ---------------------------------------------------------------------------
__global__ __launch_bounds__(256) void rerank_kernel(
    const int* __restrict__ kptr, const float* __restrict__ W2,
    const float* __restrict__ b2, const float* __restrict__ temp,
    float* __restrict__ out, int N, int B)
{
    __shared__ float qbs[Hc];
    __shared__ float w2s[Hc];
    __shared__ unsigned long long skeys[NCAND];   // 4 KB
    __shared__ unsigned long long warpmax[8];
    __shared__ unsigned long long bestsh;

    int b = blockIdx.x, t = threadIdx.x;
    int k = *kptr; if (k > KMAX) k = KMAX; if (k < 1) k = 1;

    qbs[t] = g_qb[b * Hc + t];
    w2s[t] = W2[t];
    __syncthreads();

    float invt = 1.0f / (fabsf(temp[0]) + 1e-8f);
    float bb = b2[0];
    int w = t >> 5, lane = t & 31;

    float wv[8], qv[8];
    #pragma unroll
    for (int j = 0; j < 8; j++) {
        wv[j] = w2s[lane + 32 * j];
        qv[j] = qbs[lane + 32 * j];
    }

    const unsigned long long* cands = &g_part[b * NCAND];
    for (int i = 0; i < NCAND / 8; i++) {
        int c = w * (NCAND / 8) + i;
        unsigned long long key = cands[c];
        int idx = (int)(~(unsigned int)(key & 0xffffffffu));
        if (idx < 0) idx = 0; if (idx >= N) idx = N - 1;
        const float* drow = g_da + (size_t)idx * Hc;
        float acc = 0.f;
        #pragma unroll
        for (int j = 0; j < 8; j++) {
            float x = qv[j] + drow[lane + 32 * j];
            acc = fmaf(gelu_f(x), wv[j], acc);
        }
        #pragma unroll
        for (int o = 16; o; o >>= 1)
            acc += __shfl_down_sync(0xffffffffu, acc, o);
        if (lane == 0)
            skeys[c] = pack_key((acc + bb) * invt, idx);
    }
    __syncthreads();

    unsigned long long m0 = skeys[t], m1 = skeys[t + 256];
    unsigned long long keys[KMAX];
    for (int r = 0; r < k; r++) {
        unsigned long long m = (m0 > m1) ? m0 : m1;
        #pragma unroll
        for (int o = 16; o; o >>= 1) {
            unsigned long long v = __shfl_xor_sync(0xffffffffu, m, o);
            m = (v > m) ? v : m;
        }
        if (lane == 0) warpmax[w] = m;
        __syncthreads();
        if (t == 0) {
            unsigned long long best = 0ull;
            #pragma unroll
            for (int ww = 0; ww < 8; ww++)
                best = (warpmax[ww] > best) ? warpmax[ww] : best;
            bestsh = best;
        }
        __syncthreads();
        unsigned long long best = bestsh;
        if (t == 0) keys[r] = best;
        if (m0 == best) m0 = 0ull;
        if (m1 == best) m1 = 0ull;
        __syncthreads();
    }

    if (t == 0) {
        float gv[KMAX]; int gi[KMAX];
        for (int r = 0; r < k; r++) {
            unsigned int hi = (unsigned int)(keys[r] >> 32);
            unsigned int u = (hi & 0x80000000u) ? (hi ^ 0x80000000u) : ~hi;
            gv[r] = __uint_as_float(u);
            gi[r] = (int)(~(unsigned int)(keys[r] & 0xffffffffu));
        }
        float mx = gv[0], sum = 0.f, ex[KMAX];
        for (int j = 0; j < k; j++) { ex[j] = expf(gv[j] - mx); sum += ex[j]; }
        float inv = 1.0f / sum;
        for (int j = 0; j < k; j++) {
            out[b * k + j] = (float)gi[j];            // top_idx (as float)
            out[B * k + b * k + j] = ex[j] * inv;     // probs
        }
    }
}

// ---------------------------------------------------------------------------
extern "C" void kernel_launch(void* const* d_in, const int* in_sizes, int n_in,
                              void* d_out, int out_size)
{
    const float* query = (const float*)d_in[0];
    const float* docs  = (const float*)d_in[1];
    const int*   kptr  = (const int*)d_in[2];
    const float* Wq    = (const float*)d_in[3];
    const float* bq    = (const float*)d_in[4];
    const float* lnqw  = (const float*)d_in[5];
    const float* lnqb  = (const float*)d_in[6];
    const float* Wd    = (const float*)d_in[7];
    const float* bd    = (const float*)d_in[8];
    const float* lndw  = (const float*)d_in[9];
    const float* lndb  = (const float*)d_in[10];
    const float* W1    = (const float*)d_in[11];
    const float* b1    = (const float*)d_in[12];
    const float* W2    = (const float*)d_in[13];
    const float* b2    = (const float*)d_in[14];
    const float* temp  = (const float*)d_in[15];

    int H = in_sizes[4];            // 256
    int Z = in_sizes[3] / H;        // 512
    int B = in_sizes[0] / Z;        // 32
    int N = in_sizes[1] / Z;        // 20000

    // opt-in to >48KB dynamic smem for the tensor doc kernel (attribute
    // setter: not a stream op / alloc / sync — legal under graph capture)
    cudaFuncSetAttribute(doc_kernel,
                         cudaFuncAttributeMaxDynamicSharedMemorySize,
                         DOC_SMEM_BYTES);

    query_kernel<<<B, 256>>>(query, Wq, bq, lnqw, lnqb, W1, b1);
    doc_kernel<<<(N + DPB - 1) / DPB, 256, DOC_SMEM_BYTES>>>(
        docs, Wd, bd, lndw, lndb, W1, N);
    score_kernel<<<N / SDOCS, 256>>>(W2, b2, temp, N);
    dim3 g1(SEG, B);
    topk_stage1<<<g1, 128>>>(N);
    rerank_kernel<<<B, 256>>>(kptr, W2, b2, temp, (float*)d_out, N, B);
}